// round 16
// baseline (speedup 1.0000x reference)
#include <cuda_runtime.h>
#include <cuda_fp16.h>
#include <cstdint>

#define NB 16
#define NC 64
#define NH 256
#define NW 256
#define NK 4
#define NO 64
#define HID 17
#define TEMP 34.0f
#define SLOPE 0.2f

// Scratch (device globals; allocation-free rule)
__device__ float g_pooled[NB * NC];   // zero-init; re-zeroed by att_kernel each call
__device__ float g_att[NB * NK];
// Aggregated fp16 weights, layout [b][ky][o][kx][c]  (k' = kx*64+c contiguous 192)
__device__ __align__(16) __half g_awh[NB * 3 * NO * 3 * NC];
__device__ float g_aggb[NB * NO];
// fp16 transposed input: [b][h][w][c]
__device__ __align__(16) __half g_xh[(size_t)NB * NH * NW * NC];

__device__ __forceinline__ unsigned smem_u32(const void* p) {
    unsigned a;
    asm("{ .reg .u64 t; cvta.to.shared.u64 t, %1; cvt.u32.u64 %0, t; }" : "=r"(a) : "l"(p));
    return a;
}
__device__ __forceinline__ unsigned sw128(unsigned o) { return o ^ ((o >> 3) & 0x70); }
__device__ __forceinline__ void ldmatrix_x4(unsigned& r0, unsigned& r1, unsigned& r2,
                                            unsigned& r3, unsigned addr) {
    asm volatile("ldmatrix.sync.aligned.m8n8.x4.shared.b16 {%0,%1,%2,%3}, [%4];"
                 : "=r"(r0), "=r"(r1), "=r"(r2), "=r"(r3) : "r"(addr));
}
__device__ __forceinline__ void mma16816(float* d, const unsigned* a, unsigned b0,
                                         unsigned b1) {
    asm volatile(
        "mma.sync.aligned.m16n8k16.row.col.f32.f16.f16.f32 "
        "{%0,%1,%2,%3}, {%4,%5,%6,%7}, {%8,%9}, {%0,%1,%2,%3};"
        : "+f"(d[0]), "+f"(d[1]), "+f"(d[2]), "+f"(d[3])
        : "r"(a[0]), "r"(a[1]), "r"(a[2]), "r"(a[3]), "r"(b0), "r"(b1));
}
__device__ __forceinline__ void cp16(unsigned dst, const void* src) {
    asm volatile("cp.async.ca.shared.global [%0], [%1], 16;" :: "r"(dst), "l"(src));
}
__device__ __forceinline__ void cp16z(unsigned dst, const void* src, int sz) {
    asm volatile("cp.async.ca.shared.global [%0], [%1], 16, %2;"
                 :: "r"(dst), "l"(src), "r"(sz));
}

// ---------------------------------------------------------------------------
// Kernel 0: x -> fp16 [b][h][w][c] transpose + fused avg-pool.
// ---------------------------------------------------------------------------
#define SPL_STR 66
#define SPL_SMEM (NW * SPL_STR * 2)  // 33792 B

__global__ void __launch_bounds__(256)
split_kernel(const float* __restrict__ x) {
    extern __shared__ __half sp[];
    __shared__ float psum[NC][8];
    const int bh = blockIdx.x;
    const int b = bh >> 8;
    const int tid = threadIdx.x;  // = w
    const int wrp = tid >> 5;
    const float* xb = x + ((size_t)b * NC * NH + (bh & 255)) * NW;
#pragma unroll 4
    for (int c = 0; c < NC; c++) {
        float v = xb[(size_t)c * (NH * NW) + tid];
        sp[tid * SPL_STR + c] = __float2half_rn(v);
#pragma unroll
        for (int off = 16; off; off >>= 1) v += __shfl_down_sync(0xFFFFFFFFu, v, off);
        if ((tid & 31) == 0) psum[c][wrp] = v;
    }
    __syncthreads();
    if (tid < NC) {
        float s = 0.f;
#pragma unroll
        for (int j = 0; j < 8; j++) s += psum[tid][j];
        atomicAdd(&g_pooled[b * NC + tid], s * (1.0f / (NH * NW)));
    }
    unsigned* oh = (unsigned*)(g_xh + (size_t)bh * NW * NC);
    const unsigned* sh32 = (const unsigned*)sp;
#pragma unroll
    for (int i = tid; i < NW * 32; i += 256) {
        int w = i >> 5, c2 = i & 31;
        oh[w * 32 + c2] = sh32[w * 33 + c2];
    }
}

// ---------------------------------------------------------------------------
// Kernel 2: attention MLP + softmax (re-zeroes g_pooled for graph replay)
// ---------------------------------------------------------------------------
__global__ void att_kernel(const float* __restrict__ fc1,
                           const float* __restrict__ fc2,
                           const float* __restrict__ fc2b) {
    __shared__ float sp[NB * NC];
    __shared__ float sf1[HID * NC];
    __shared__ float sh[NB][HID];
    int t = threadIdx.x;
    for (int i = t; i < NB * NC; i += blockDim.x) sp[i] = g_pooled[i];
    for (int i = t; i < HID * NC; i += blockDim.x) sf1[i] = fc1[i];
    __syncthreads();
    for (int i = t; i < NB * NC; i += blockDim.x) g_pooled[i] = 0.f;
    if (t < NB * HID) {
        int b = t / HID, j = t % HID;
        float s = 0.f;
#pragma unroll
        for (int c = 0; c < NC; c++) s += sp[b * NC + c] * sf1[j * NC + c];
        sh[b][j] = s >= 0.f ? s : SLOPE * s;
    }
    __syncthreads();
    if (t < NB) {
        int b = t;
        float lg[NK];
        float m = -1e30f;
#pragma unroll
        for (int k = 0; k < NK; k++) {
            float s = fc2b[k];
#pragma unroll
            for (int j = 0; j < HID; j++) s += sh[b][j] * fc2[k * HID + j];
            lg[k] = s / TEMP;
            m = fmaxf(m, lg[k]);
        }
        float den = 0.f, e[NK];
#pragma unroll
        for (int k = 0; k < NK; k++) { e[k] = expf(lg[k] - m); den += e[k]; }
        float inv = 1.0f / den;
#pragma unroll
        for (int k = 0; k < NK; k++) g_att[b * NK + k] = e[k] * inv;
    }
}

// ---------------------------------------------------------------------------
// Kernel 3: aggregate weights -> fp16, layout [b][ky][o][kx][c]
// ---------------------------------------------------------------------------
__global__ void agg_kernel(const float* __restrict__ weight,  // [K][O][I][3][3]
                           const float* __restrict__ bias_k) {
    int idx = blockIdx.x * 256 + threadIdx.x;
    const int TOT = NB * 3 * NO * 3 * NC;  // 589824
    if (idx < TOT) {
        int c = idx & 63;
        int t1 = idx >> 6;
        int kx = t1 % 3; t1 /= 3;
        int o = t1 & 63; t1 >>= 6;
        int ky = t1 % 3;
        int b = t1 / 3;
        const int KS = NO * NC * 9;
        int wb = (o * NC + c) * 9 + ky * 3 + kx;
        float s = g_att[b * NK + 0] * weight[wb] +
                  g_att[b * NK + 1] * weight[wb + KS] +
                  g_att[b * NK + 2] * weight[wb + 2 * KS] +
                  g_att[b * NK + 3] * weight[wb + 3 * KS];
        g_awh[idx] = __float2half_rn(s);
    }
    if (idx < NB * NO) {
        int b = idx >> 6, o = idx & 63;
        float s = 0.f;
#pragma unroll
        for (int k = 0; k < NK; k++) s += g_att[b * NK + k] * bias_k[k * NO + o];
        g_aggb[idx] = s;
    }
}

// ---------------------------------------------------------------------------
// Kernel 4: mma.sync fp16 conv. 256 thr, 8 warps (8m x 1n), 2 CTAs/SM.
// CTA = (b, row-pair, xhalf, nhalf): 2 rows x 128 px x 32 outs.
// X: 4 staged rows (SW128, 66.6 KB); B: 3 ky x 32 o (38.4 KB); ONE barrier.
// Co-resident CTA hides the staging prologue.
// ---------------------------------------------------------------------------
#define XPLANE (4 * 130 * 128)            // 66560 B
#define OFF_B XPLANE
#define BSTR 400                          // bytes per o-row (192*2 + 16 pad)
#define BPL32 (32 * BSTR)                 // 12800 B per ky plane (32 outs)
#define CONV_SMEM (OFF_B + 3 * BPL32)     // 104960 B  -> 2 CTAs/SM

__global__ void __launch_bounds__(256, 2)
conv_kernel(float* __restrict__ out) {
    extern __shared__ char smem[];
    const unsigned sb = smem_u32(smem);
    const int tid = threadIdx.x;
    const int lane = tid & 31, wm = tid >> 5;   // 8 m-warps
    const int nhalf = blockIdx.y;
    const int b = blockIdx.z;
    const int y0 = (blockIdx.x >> 1) * 2;
    const int x0 = (blockIdx.x & 1) * 128;

    // ---- stage X (4 rows x 130 px x 128B, swizzled) ----
    {
        const size_t bbase = (size_t)b * NH * NW * NC;
        for (int i = tid; i < 4160; i += 256) {
            int ch = i & 7;
            int rc = i >> 3;                    // r*130 + cl, r in [0,4)
            int r = rc / 130, cl = rc - r * 130;
            int gy = y0 - 1 + r, gx = x0 - 1 + cl;
            bool ok = ((unsigned)gy < 256u) && ((unsigned)gx < 256u);
            const void* src = g_xh + bbase +
                              ((size_t)(ok ? (gy * 256 + gx) : 0) * 64) + ch * 8;
            unsigned o = (unsigned)(rc * 128 + ch * 16);
            cp16z(sb + sw128(o), src, ok ? 16 : 0);
        }
    }
    // ---- stage B: 3 ky planes x 32 outs (2304 chunks of 16B) ----
    {
        const __half* awh = g_awh + (size_t)(b * 3) * (NO * 192) + nhalf * 32 * 192;
#pragma unroll
        for (int j = 0; j < 9; j++) {
            int q = tid + j * 256;
            int o3 = q / 24, ck = q - o3 * 24;  // o3 in [0,96): ky*32 + o32
            int ky = o3 >> 5, o32 = o3 & 31;
            const void* src = awh + (ky * 64 + o32) * 192 + ck * 8;
            unsigned dst = sb + OFF_B + o3 * BSTR + ck * 16;
            cp16(dst, src);
        }
        asm volatile("cp.async.commit_group;");
    }
    asm volatile("cp.async.wait_group 0;");
    __syncthreads();  // the only barrier in the kernel

    float acc[2][4][4];  // [rw][tn][frag]
#pragma unroll
    for (int rw = 0; rw < 2; rw++)
#pragma unroll
        for (int tn = 0; tn < 4; tn++)
#pragma unroll
            for (int r = 0; r < 4; r++) acc[rw][tn][r] = 0.f;

    // A lane addressing (m16 x k16 tile per x4)
    const int apx = wm * 16 + (lane & 15);
    const unsigned aklo = (lane & 16) ? 16u : 0u;
    // B lane addressing (n16 x k16 per x4; two n16 groups cover the 32 outs)
    const int bq = lane >> 3;
    const int brow = ((bq & 2) << 2) + (lane & 7);
    const unsigned bklo = (unsigned)((bq & 1) * 16);
    const unsigned brbase = sb + OFF_B + (unsigned)(brow * BSTR) + bklo;

#pragma unroll 1
    for (int kc = 0; kc < 12; kc++) {
        // Load all B fragments for this kc: 3 ky x 2 n-groups
        unsigned B0[3][4], B1[3][4];
#pragma unroll
        for (int ky = 0; ky < 3; ky++) {
            unsigned b0 = brbase + (unsigned)(ky * BPL32) + kc * 32;
            ldmatrix_x4(B0[ky][0], B0[ky][1], B0[ky][2], B0[ky][3], b0);
            ldmatrix_x4(B1[ky][0], B1[ky][1], B1[ky][2], B1[ky][3], b0 + 16 * BSTR);
        }
        // Each x-row loaded once; contributes to out rows rw = r - ky in [0,2)
#pragma unroll
        for (int r = 0; r < 4; r++) {
            unsigned o_ = (unsigned)((r * 130 + apx) * 128 + kc * 32) + aklo;
            unsigned hc[4];
            ldmatrix_x4(hc[0], hc[1], hc[2], hc[3], sb + sw128(o_));
#pragma unroll
            for (int ky = 0; ky < 3; ky++) {
                const int rw = r - ky;
                if (rw >= 0 && rw < 2) {
                    mma16816(acc[rw][0], hc, B0[ky][0], B0[ky][1]);
                    mma16816(acc[rw][1], hc, B0[ky][2], B0[ky][3]);
                    mma16816(acc[rw][2], hc, B1[ky][0], B1[ky][1]);
                    mma16816(acc[rw][3], hc, B1[ky][2], B1[ky][3]);
                }
            }
        }
    }

    // ---- epilogue: bias + store (2 rows x 32 outs) ----
    const int m0 = x0 + wm * 16 + (lane >> 2);
#pragma unroll
    for (int rw = 0; rw < 2; rw++) {
        const int y = y0 + rw;
#pragma unroll
        for (int tn = 0; tn < 4; tn++) {
            int n0 = nhalf * 32 + tn * 8 + (lane & 3) * 2;
            float bv0 = g_aggb[b * NO + n0];
            float bv1 = g_aggb[b * NO + n0 + 1];
            size_t p0 = ((size_t)(b * NO + n0) * NH + y) * NW;
            size_t p1 = ((size_t)(b * NO + n0 + 1) * NH + y) * NW;
            out[p0 + m0] = acc[rw][tn][0] + bv0;
            out[p1 + m0] = acc[rw][tn][1] + bv1;
            out[p0 + m0 + 8] = acc[rw][tn][2] + bv0;
            out[p1 + m0 + 8] = acc[rw][tn][3] + bv1;
        }
    }
}

// ---------------------------------------------------------------------------
extern "C" void kernel_launch(void* const* d_in, const int* in_sizes, int n_in,
                              void* d_out, int out_size) {
    const float* x      = (const float*)d_in[0];
    const float* fc1_w  = (const float*)d_in[1];
    const float* fc2_w  = (const float*)d_in[2];
    const float* fc2_b  = (const float*)d_in[3];
    const float* weight = (const float*)d_in[4];
    const float* bias_k = (const float*)d_in[5];
    float* out = (float*)d_out;

    cudaFuncSetAttribute(split_kernel, cudaFuncAttributeMaxDynamicSharedMemorySize,
                         SPL_SMEM);
    cudaFuncSetAttribute(conv_kernel, cudaFuncAttributeMaxDynamicSharedMemorySize,
                         CONV_SMEM);

    split_kernel<<<NB * NH, 256, SPL_SMEM>>>(x);
    att_kernel<<<1, 288>>>(fc1_w, fc2_w, fc2_b);
    agg_kernel<<<(NB * 3 * NO * 3 * NC + 255) / 256, 256>>>(weight, bias_k);
    conv_kernel<<<dim3(NH, 2, NB), 256, CONV_SMEM>>>(out);
}

// round 17
// speedup vs baseline: 1.0315x; 1.0315x over previous
#include <cuda_runtime.h>
#include <cuda_fp16.h>
#include <cstdint>

#define NB 16
#define NC 64
#define NH 256
#define NW 256
#define NK 4
#define NO 64
#define HID 17
#define TEMP 34.0f
#define SLOPE 0.2f

// Scratch (device globals; allocation-free rule)
__device__ float g_pooled[NB * NC];   // zero-init; re-zeroed by att_kernel each call
__device__ float g_att[NB * NK];
// Aggregated fp16 weights, layout [b][ky][o][kx][c]  (k' = kx*64+c contiguous 192)
__device__ __align__(16) __half g_awh[NB * 3 * NO * 3 * NC];
__device__ float g_aggb[NB * NO];
// fp16 transposed input: [b][h][w][c]
__device__ __align__(16) __half g_xh[(size_t)NB * NH * NW * NC];

__device__ __forceinline__ unsigned smem_u32(const void* p) {
    unsigned a;
    asm("{ .reg .u64 t; cvta.to.shared.u64 t, %1; cvt.u32.u64 %0, t; }" : "=r"(a) : "l"(p));
    return a;
}
__device__ __forceinline__ unsigned sw128(unsigned o) { return o ^ ((o >> 3) & 0x70); }
__device__ __forceinline__ void ldmatrix_x4(unsigned& r0, unsigned& r1, unsigned& r2,
                                            unsigned& r3, unsigned addr) {
    asm volatile("ldmatrix.sync.aligned.m8n8.x4.shared.b16 {%0,%1,%2,%3}, [%4];"
                 : "=r"(r0), "=r"(r1), "=r"(r2), "=r"(r3) : "r"(addr));
}
__device__ __forceinline__ void mma16816(float* d, const unsigned* a, unsigned b0,
                                         unsigned b1) {
    asm volatile(
        "mma.sync.aligned.m16n8k16.row.col.f32.f16.f16.f32 "
        "{%0,%1,%2,%3}, {%4,%5,%6,%7}, {%8,%9}, {%0,%1,%2,%3};"
        : "+f"(d[0]), "+f"(d[1]), "+f"(d[2]), "+f"(d[3])
        : "r"(a[0]), "r"(a[1]), "r"(a[2]), "r"(a[3]), "r"(b0), "r"(b1));
}
__device__ __forceinline__ void cp16(unsigned dst, const void* src) {
    asm volatile("cp.async.ca.shared.global [%0], [%1], 16;" :: "r"(dst), "l"(src));
}
__device__ __forceinline__ void cp16z(unsigned dst, const void* src, int sz) {
    asm volatile("cp.async.ca.shared.global [%0], [%1], 16, %2;"
                 :: "r"(dst), "l"(src), "r"(sz));
}

// ---------------------------------------------------------------------------
// Kernel 0: x -> fp16 [b][h][w][c] transpose + fused avg-pool.
// ---------------------------------------------------------------------------
#define SPL_STR 66
#define SPL_SMEM (NW * SPL_STR * 2)  // 33792 B

__global__ void __launch_bounds__(256)
split_kernel(const float* __restrict__ x) {
    extern __shared__ __half sp[];
    __shared__ float psum[NC][8];
    const int bh = blockIdx.x;
    const int b = bh >> 8;
    const int tid = threadIdx.x;  // = w
    const int wrp = tid >> 5;
    const float* xb = x + ((size_t)b * NC * NH + (bh & 255)) * NW;
#pragma unroll 4
    for (int c = 0; c < NC; c++) {
        float v = xb[(size_t)c * (NH * NW) + tid];
        sp[tid * SPL_STR + c] = __float2half_rn(v);
#pragma unroll
        for (int off = 16; off; off >>= 1) v += __shfl_down_sync(0xFFFFFFFFu, v, off);
        if ((tid & 31) == 0) psum[c][wrp] = v;
    }
    __syncthreads();
    if (tid < NC) {
        float s = 0.f;
#pragma unroll
        for (int j = 0; j < 8; j++) s += psum[tid][j];
        atomicAdd(&g_pooled[b * NC + tid], s * (1.0f / (NH * NW)));
    }
    unsigned* oh = (unsigned*)(g_xh + (size_t)bh * NW * NC);
    const unsigned* sh32 = (const unsigned*)sp;
#pragma unroll
    for (int i = tid; i < NW * 32; i += 256) {
        int w = i >> 5, c2 = i & 31;
        oh[w * 32 + c2] = sh32[w * 33 + c2];
    }
}

// ---------------------------------------------------------------------------
// Kernel 2: attention MLP + softmax (re-zeroes g_pooled for graph replay)
// ---------------------------------------------------------------------------
__global__ void att_kernel(const float* __restrict__ fc1,
                           const float* __restrict__ fc2,
                           const float* __restrict__ fc2b) {
    __shared__ float sp[NB * NC];
    __shared__ float sf1[HID * NC];
    __shared__ float sh[NB][HID];
    int t = threadIdx.x;
    for (int i = t; i < NB * NC; i += blockDim.x) sp[i] = g_pooled[i];
    for (int i = t; i < HID * NC; i += blockDim.x) sf1[i] = fc1[i];
    __syncthreads();
    for (int i = t; i < NB * NC; i += blockDim.x) g_pooled[i] = 0.f;
    if (t < NB * HID) {
        int b = t / HID, j = t % HID;
        float s = 0.f;
#pragma unroll
        for (int c = 0; c < NC; c++) s += sp[b * NC + c] * sf1[j * NC + c];
        sh[b][j] = s >= 0.f ? s : SLOPE * s;
    }
    __syncthreads();
    if (t < NB) {
        int b = t;
        float lg[NK];
        float m = -1e30f;
#pragma unroll
        for (int k = 0; k < NK; k++) {
            float s = fc2b[k];
#pragma unroll
            for (int j = 0; j < HID; j++) s += sh[b][j] * fc2[k * HID + j];
            lg[k] = s / TEMP;
            m = fmaxf(m, lg[k]);
        }
        float den = 0.f, e[NK];
#pragma unroll
        for (int k = 0; k < NK; k++) { e[k] = expf(lg[k] - m); den += e[k]; }
        float inv = 1.0f / den;
#pragma unroll
        for (int k = 0; k < NK; k++) g_att[b * NK + k] = e[k] * inv;
    }
}

// ---------------------------------------------------------------------------
// Kernel 3: aggregate weights -> fp16, layout [b][ky][o][kx][c]
// ---------------------------------------------------------------------------
__global__ void agg_kernel(const float* __restrict__ weight,  // [K][O][I][3][3]
                           const float* __restrict__ bias_k) {
    int idx = blockIdx.x * 256 + threadIdx.x;
    const int TOT = NB * 3 * NO * 3 * NC;  // 589824
    if (idx < TOT) {
        int c = idx & 63;
        int t1 = idx >> 6;
        int kx = t1 % 3; t1 /= 3;
        int o = t1 & 63; t1 >>= 6;
        int ky = t1 % 3;
        int b = t1 / 3;
        const int KS = NO * NC * 9;
        int wb = (o * NC + c) * 9 + ky * 3 + kx;
        float s = g_att[b * NK + 0] * weight[wb] +
                  g_att[b * NK + 1] * weight[wb + KS] +
                  g_att[b * NK + 2] * weight[wb + 2 * KS] +
                  g_att[b * NK + 3] * weight[wb + 3 * KS];
        g_awh[idx] = __float2half_rn(s);
    }
    if (idx < NB * NO) {
        int b = idx >> 6, o = idx & 63;
        float s = 0.f;
#pragma unroll
        for (int k = 0; k < NK; k++) s += g_att[b * NK + k] * bias_k[k * NO + o];
        g_aggb[idx] = s;
    }
}

// ---------------------------------------------------------------------------
// Kernel 4: strip-persistent mma.sync fp16 conv. 512 thr, 16 warps (8m x 2n).
// CTA = (b, xhalf, 16-row strip): B staged ONCE; X in a 6-slot row ring,
// 2 new rows staged per 2-row iteration under compute. 1 barrier/iter.
// ---------------------------------------------------------------------------
#define SLOT (130 * 128)                  // 16640 B per X row slot
#define OFF_B (6 * SLOT)                  // 99840
#define BSTR 400                          // bytes per o-row (192*2 + 16 pad)
#define BPL (64 * BSTR)                   // 25600 B per ky plane
#define CONV_SMEM (OFF_B + 3 * BPL)       // 176640 B
#define STRIP 16                          // output rows per CTA
#define NITER (STRIP / 2)                 // 8

__global__ void __launch_bounds__(512, 1)
conv_kernel(float* __restrict__ out) {
    extern __shared__ char smem[];
    const unsigned sb = smem_u32(smem);
    const int tid = threadIdx.x;
    const int lane = tid & 31, wid = tid >> 5;
    const int wm = wid & 7, wn = wid >> 3;   // 8m x 2n
    const int strip = blockIdx.x >> 1;
    const int x0 = (blockIdx.x & 1) * 128;
    const int b = blockIdx.y;
    const int y0 = strip * STRIP;
    const size_t bbase = (size_t)b * NH * NW * NC;

    // ---- STAGE_X_ROWS(ri0, nrows): rows ri (rel: gy = y0-1+ri) into slot ri%6
#define STAGE_X(RI0, NROWS)                                                      \
    {                                                                            \
        const int total = (NROWS) * 1040;                                        \
        for (int q = tid; q < total; q += 512) {                                 \
            int ro = q / 1040, rem = q - ro * 1040;                              \
            int cl = rem >> 3, ch = rem & 7;                                     \
            int ri = (RI0) + ro;                                                 \
            int gy = y0 - 1 + ri, gx = x0 - 1 + cl;                              \
            bool ok = ((unsigned)gy < 256u) && ((unsigned)gx < 256u);            \
            const void* src = g_xh + bbase +                                     \
                              ((size_t)(ok ? (gy * 256 + gx) : 0) * 64) + ch * 8;\
            unsigned dst = sb + (ri % 6) * SLOT +                                \
                           sw128((unsigned)(cl * 128 + ch * 16));                \
            cp16z(dst, src, ok ? 16 : 0);                                        \
        }                                                                        \
    }

    // ---- prologue: X rows ri=0..3 and all B, one commit ----
    STAGE_X(0, 4);
    {
        const __half* awh = g_awh + (size_t)(b * 3) * (NO * 192);
#pragma unroll
        for (int j = 0; j < 9; j++) {
            int q = tid + j * 512;
            int o = q / 24, ck = q - o * 24;   // o in [0,192): ky*64 + och
            const void* src = awh + o * 192 + ck * 8;
            unsigned dst = sb + OFF_B + o * BSTR + ck * 16;
            cp16(dst, src);
        }
        asm volatile("cp.async.commit_group;");
    }

    // A lane addressing (m16 x k16 tile per x4)
    const int apx = wm * 16 + (lane & 15);
    const unsigned aklo = (lane & 16) ? 16u : 0u;
    const unsigned albase = sw128 ? 0u : 0u;  // (placeholder, not used)
    // B lane addressing (n16 x k16 per x4; two n-groups for n=32)
    const int bq = lane >> 3;
    const int brow = ((bq & 2) << 2) + (lane & 7);
    const unsigned bklo = (unsigned)((bq & 1) * 16);
    const unsigned brbase = sb + OFF_B + (unsigned)((wn * 32 + brow) * BSTR) + bklo;

    // bias hoisted (per-thread 8 values)
    float bv[4][2];
#pragma unroll
    for (int tn = 0; tn < 4; tn++) {
        int n0 = wn * 32 + tn * 8 + (lane & 3) * 2;
        bv[tn][0] = g_aggb[b * NO + n0];
        bv[tn][1] = g_aggb[b * NO + n0 + 1];
    }
    const int m0 = x0 + wm * 16 + (lane >> 2);

#pragma unroll 1
    for (int j = 0; j < NITER; j++) {
        asm volatile("cp.async.wait_group 0;");
        __syncthreads();  // staged rows (and B on j=0) visible; ring slots free
        if (j < NITER - 1) {
            STAGE_X(2 * j + 4, 2);
            asm volatile("cp.async.commit_group;");
        }

        float acc[2][4][4];
#pragma unroll
        for (int rw = 0; rw < 2; rw++)
#pragma unroll
            for (int tn = 0; tn < 4; tn++)
#pragma unroll
                for (int r = 0; r < 4; r++) acc[rw][tn][r] = 0.f;

#pragma unroll 2
        for (int kc = 0; kc < 12; kc++) {
            unsigned B0[3][4], B1[3][4];
#pragma unroll
            for (int ky = 0; ky < 3; ky++) {
                unsigned b0 = brbase + (unsigned)(ky * BPL) + kc * 32;
                ldmatrix_x4(B0[ky][0], B0[ky][1], B0[ky][2], B0[ky][3], b0);
                ldmatrix_x4(B1[ky][0], B1[ky][1], B1[ky][2], B1[ky][3], b0 + 16 * BSTR);
            }
#pragma unroll
            for (int r4 = 0; r4 < 4; r4++) {
                const int ri = 2 * j + r4;
                unsigned ad = sb + (ri % 6) * SLOT +
                              sw128((unsigned)(apx * 128 + kc * 32) + aklo);
                unsigned hc[4];
                ldmatrix_x4(hc[0], hc[1], hc[2], hc[3], ad);
#pragma unroll
                for (int ky = 0; ky < 3; ky++) {
                    const int rw = r4 - ky;
                    if (rw >= 0 && rw < 2) {
                        mma16816(acc[rw][0], hc, B0[ky][0], B0[ky][1]);
                        mma16816(acc[rw][1], hc, B0[ky][2], B0[ky][3]);
                        mma16816(acc[rw][2], hc, B1[ky][0], B1[ky][1]);
                        mma16816(acc[rw][3], hc, B1[ky][2], B1[ky][3]);
                    }
                }
            }
        }

        // ---- epilogue for this iteration (2 rows) ----
#pragma unroll
        for (int rw = 0; rw < 2; rw++) {
            const int y = y0 + 2 * j + rw;
#pragma unroll
            for (int tn = 0; tn < 4; tn++) {
                int n0 = wn * 32 + tn * 8 + (lane & 3) * 2;
                size_t p0 = ((size_t)(b * NO + n0) * NH + y) * NW;
                size_t p1 = ((size_t)(b * NO + n0 + 1) * NH + y) * NW;
                out[p0 + m0] = acc[rw][tn][0] + bv[tn][0];
                out[p1 + m0] = acc[rw][tn][1] + bv[tn][1];
                out[p0 + m0 + 8] = acc[rw][tn][2] + bv[tn][0];
                out[p1 + m0 + 8] = acc[rw][tn][3] + bv[tn][1];
            }
        }
    }
#undef STAGE_X
}

// ---------------------------------------------------------------------------
extern "C" void kernel_launch(void* const* d_in, const int* in_sizes, int n_in,
                              void* d_out, int out_size) {
    const float* x      = (const float*)d_in[0];
    const float* fc1_w  = (const float*)d_in[1];
    const float* fc2_w  = (const float*)d_in[2];
    const float* fc2_b  = (const float*)d_in[3];
    const float* weight = (const float*)d_in[4];
    const float* bias_k = (const float*)d_in[5];
    float* out = (float*)d_out;

    cudaFuncSetAttribute(split_kernel, cudaFuncAttributeMaxDynamicSharedMemorySize,
                         SPL_SMEM);
    cudaFuncSetAttribute(conv_kernel, cudaFuncAttributeMaxDynamicSharedMemorySize,
                         CONV_SMEM);

    split_kernel<<<NB * NH, 256, SPL_SMEM>>>(x);
    att_kernel<<<1, 288>>>(fc1_w, fc2_w, fc2_b);
    agg_kernel<<<(NB * 3 * NO * 3 * NC + 255) / 256, 256>>>(weight, bias_k);
    conv_kernel<<<dim3((NH / STRIP) * 2, NB), 512, CONV_SMEM>>>(out);
}